// round 15
// baseline (speedup 1.0000x reference)
#include <cuda_runtime.h>
#include <cuda_fp16.h>
#include <stdint.h>

#define TOKENS 16384
#define KDIM   2048
#define EDIM   64
#define TOPK   8
#define BM     64
#define BK     32
#define KSPLIT 4
#define NITH   16              // k-tiles per split (4 x 16 x 32 = 2048)
#define NMB    (TOKENS / BM)   // 256 m-blocks
#define WSCALE 1024.0f
#define WINV   (1.0f / 1024.0f)
#define PHALF  ((size_t)TOKENS * EDIM)

// per-stage staging: Ahi@0 (4KB), Alo@4096, Bhi@8192, Blo@12288  -> 16KB; x2 stages
#define STAGE_B 16384
#define SMEM_K1 (2 * STAGE_B)

__device__ float g_part[KSPLIT][TOKENS * EDIM];   // 16.8 MB scratch (L2-resident)
__device__ int   g_cnt[NMB];                      // completion counters (zero-init)

__device__ __forceinline__ uint32_t pack2h(__half a, __half b) {
    return (uint32_t)__half_as_ushort(a) | ((uint32_t)__half_as_ushort(b) << 16);
}

__device__ __forceinline__ void mma_f16(float c[4],
                                        uint32_t a0, uint32_t a1, uint32_t a2, uint32_t a3,
                                        uint32_t b0, uint32_t b1) {
    asm volatile(
        "mma.sync.aligned.m16n8k16.row.col.f32.f16.f16.f32 "
        "{%0,%1,%2,%3},{%4,%5,%6,%7},{%8,%9},{%0,%1,%2,%3};\n"
        : "+f"(c[0]), "+f"(c[1]), "+f"(c[2]), "+f"(c[3])
        : "r"(a0), "r"(a1), "r"(a2), "r"(a3), "r"(b0), "r"(b1));
}

__device__ __forceinline__ void split16(float v, __half& h, __half& l) {
    h = __float2half_rn(v);
    l = __float2half_rn(v - __half2float(h));
}

// ---------------- fused: quarter-K GEMM + last-arriver top-k finisher ----------------
__global__ void __launch_bounds__(128, 4)
gemm_fused(const float* __restrict__ X, const float* __restrict__ W,
           const float* __restrict__ bias, float* __restrict__ out)
{
    __shared__ char smem[SMEM_K1];

    const int tid  = threadIdx.x;
    const int wrp  = tid >> 5;
    const int lane = tid & 31;
    const int mblk = blockIdx.x >> 2;        // m-block
    const int spl  = blockIdx.x & 3;         // k-split
    const int mb   = mblk * BM;
    const int kb   = spl * NITH;             // first k-tile of this split

    const int g  = lane >> 2;
    const int c  = lane & 3;
    const int s4 = ((g >> 1) & 3) << 2;
    const int R0 = (wrp >> 1) << 5;          // warp row base (0/32)
    const int N0 = (wrp & 1) << 5;           // warp col base (0/32)

    // staging decomposition (128 threads)
    const int ar  = tid >> 1;                // A row 0..63
    const int akw = (tid & 1) << 3;          // A word base 0/8
    const int asw = ((ar >> 1) & 3) << 2;
    const int bn  = tid & 63;                // B expert 0..63
    const int bkq = tid >> 6;                // B k-quarter 0/1
    const int bkw = bkq << 3;
    const int bsw = ((bn >> 1) & 3) << 2;

    float acc[2][4][4];
    #pragma unroll
    for (int mt = 0; mt < 2; ++mt)
        #pragma unroll
        for (int j = 0; j < 4; ++j)
            #pragma unroll
            for (int q = 0; q < 4; ++q) acc[mt][j][q] = 0.f;

    float4 xa[4];
    float  wv[16];
    {   // prefetch tile 0 of this split
        const float* xp = X + (size_t)(mb + ar) * KDIM + kb * BK + (akw << 1);
        #pragma unroll
        for (int p = 0; p < 4; ++p) xa[p] = *(const float4*)(xp + 4 * p);
        const float* wp = W + (size_t)(kb * BK + bkq * 16) * EDIM + bn;
        #pragma unroll
        for (int i = 0; i < 16; ++i) wv[i] = wp[(size_t)i * EDIM];
    }

    #pragma unroll 1
    for (int it = 0; it < NITH; ++it) {
        char* Ahi = smem + (it & 1) * STAGE_B;
        char* Bhi = Ahi + 8192;

        // ---- store staged tile (fp16 hi/lo split), swizzled ----
        {
            float v[16] = {xa[0].x, xa[0].y, xa[0].z, xa[0].w,
                           xa[1].x, xa[1].y, xa[1].z, xa[1].w,
                           xa[2].x, xa[2].y, xa[2].z, xa[2].w,
                           xa[3].x, xa[3].y, xa[3].z, xa[3].w};
            uint32_t ph[8], pl[8];
            #pragma unroll
            for (int i = 0; i < 8; ++i) {
                __half h0, l0, h1, l1;
                split16(v[2 * i],     h0, l0);
                split16(v[2 * i + 1], h1, l1);
                ph[i] = pack2h(h0, h1);
                pl[i] = pack2h(l0, l1);
            }
            char* pa = Ahi + ar * 64;
            const int o0 = ((akw)     ^ asw) << 2;
            const int o1 = ((akw + 4) ^ asw) << 2;
            *(uint4*)(pa + o0)        = make_uint4(ph[0], ph[1], ph[2], ph[3]);
            *(uint4*)(pa + o1)        = make_uint4(ph[4], ph[5], ph[6], ph[7]);
            *(uint4*)(pa + 4096 + o0) = make_uint4(pl[0], pl[1], pl[2], pl[3]);
            *(uint4*)(pa + 4096 + o1) = make_uint4(pl[4], pl[5], pl[6], pl[7]);
        }
        {
            uint32_t ph[8], pl[8];
            #pragma unroll
            for (int i = 0; i < 8; ++i) {
                __half h0, l0, h1, l1;
                split16(wv[2 * i]     * WSCALE, h0, l0);
                split16(wv[2 * i + 1] * WSCALE, h1, l1);
                ph[i] = pack2h(h0, h1);
                pl[i] = pack2h(l0, l1);
            }
            char* pb = Bhi + bn * 64;
            const int o0 = ((bkw)     ^ bsw) << 2;
            const int o1 = ((bkw + 4) ^ bsw) << 2;
            *(uint4*)(pb + o0)        = make_uint4(ph[0], ph[1], ph[2], ph[3]);
            *(uint4*)(pb + o1)        = make_uint4(ph[4], ph[5], ph[6], ph[7]);
            *(uint4*)(pb + 4096 + o0) = make_uint4(pl[0], pl[1], pl[2], pl[3]);
            *(uint4*)(pb + 4096 + o1) = make_uint4(pl[4], pl[5], pl[6], pl[7]);
        }
        __syncthreads();   // single barrier per iteration (double buffer)

        // ---- prefetch next tile ----
        if (it + 1 < NITH) {
            const int nk = kb + it + 1;
            const float* xp = X + (size_t)(mb + ar) * KDIM + nk * BK + (akw << 1);
            #pragma unroll
            for (int p = 0; p < 4; ++p) xa[p] = *(const float4*)(xp + 4 * p);
            const float* wp = W + (size_t)(nk * BK + bkq * 16) * EDIM + bn;
            #pragma unroll
            for (int i = 0; i < 16; ++i) wv[i] = wp[(size_t)i * EDIM];
        }

        // ---- compute: 2 k-chunks; preload frags, product-major MMA issue ----
        #pragma unroll
        for (int kc = 0; kc < 2; ++kc) {
            const int o0 = ((kc * 8 + c)     ^ s4) << 2;
            const int o1 = ((kc * 8 + c + 4) ^ s4) << 2;
            uint32_t ah[2][4], al[2][4];
            #pragma unroll
            for (int mt = 0; mt < 2; ++mt) {
                const char* pa = Ahi + (R0 + mt * 16 + g) * 64;
                ah[mt][0] = *(const uint32_t*)(pa + o0);
                ah[mt][1] = *(const uint32_t*)(pa + 512 + o0);
                ah[mt][2] = *(const uint32_t*)(pa + o1);
                ah[mt][3] = *(const uint32_t*)(pa + 512 + o1);
                al[mt][0] = *(const uint32_t*)(pa + 4096 + o0);
                al[mt][1] = *(const uint32_t*)(pa + 4608 + o0);
                al[mt][2] = *(const uint32_t*)(pa + 4096 + o1);
                al[mt][3] = *(const uint32_t*)(pa + 4608 + o1);
            }
            uint32_t bh[4][2], bl[4][2];
            #pragma unroll
            for (int j = 0; j < 4; ++j) {
                const char* pb = Bhi + (N0 + j * 8 + g) * 64;
                bh[j][0] = *(const uint32_t*)(pb + o0);
                bh[j][1] = *(const uint32_t*)(pb + o1);
                bl[j][0] = *(const uint32_t*)(pb + 4096 + o0);
                bl[j][1] = *(const uint32_t*)(pb + 4096 + o1);
            }
            #pragma unroll
            for (int j = 0; j < 4; ++j)
                #pragma unroll
                for (int mt = 0; mt < 2; ++mt)
                    mma_f16(acc[mt][j], ah[mt][0], ah[mt][1], ah[mt][2], ah[mt][3],
                            bh[j][0], bh[j][1]);
            #pragma unroll
            for (int j = 0; j < 4; ++j)
                #pragma unroll
                for (int mt = 0; mt < 2; ++mt)
                    mma_f16(acc[mt][j], al[mt][0], al[mt][1], al[mt][2], al[mt][3],
                            bh[j][0], bh[j][1]);
            #pragma unroll
            for (int j = 0; j < 4; ++j)
                #pragma unroll
                for (int mt = 0; mt < 2; ++mt)
                    mma_f16(acc[mt][j], ah[mt][0], ah[mt][1], ah[mt][2], ah[mt][3],
                            bl[j][0], bl[j][1]);
        }
    }

    // ---- write raw partial sums (scaled by WSCALE) to scratch ----
    float* pbase = g_part[spl] + (size_t)mb * EDIM;
    #pragma unroll
    for (int mt = 0; mt < 2; ++mt)
        #pragma unroll
        for (int j = 0; j < 4; ++j) {
            const int col = N0 + j * 8 + 2 * c;
            const int r0  = R0 + mt * 16 + g;
            *(float2*)&pbase[(size_t)r0 * EDIM + col] =
                make_float2(acc[mt][j][0], acc[mt][j][1]);
            *(float2*)&pbase[(size_t)(r0 + 8) * EDIM + col] =
                make_float2(acc[mt][j][2], acc[mt][j][3]);
        }

    // ---- completion protocol: last arriver finishes this m-block ----
    __threadfence();
    __syncthreads();                          // all STGs issued, smem dead
    int* flagp = (int*)smem;
    if (tid == 0) {
        const int old = atomicAdd(&g_cnt[mblk], 1);
        *flagp = (old == KSPLIT - 1) ? 1 : 0;
    }
    __syncthreads();
    if (*flagp) {
        __threadfence();                      // acquire: all splits' partials visible
        const float b0v = bias[lane];
        const float b1v = bias[lane + 32];
        float* maskp = out + PHALF;
        // warp w handles tokens mb + w*16 .. +15
        for (int r = 0; r < 16; ++r) {
            const int row = mb + (wrp << 4) + r;
            const size_t gt = (size_t)row * EDIM;
            float p0 = 0.f, p1 = 0.f;
            #pragma unroll
            for (int s = 0; s < KSPLIT; ++s) {
                p0 += g_part[s][gt + lane];
                p1 += g_part[s][gt + lane + 32];
            }
            // fabsf clears a possible -0 so fp32 bits are order-isomorphic to value
            const float v0 = fabsf(fmaxf(fmaf(p0, WINV, b0v), 0.f));
            const float v1 = fabsf(fmaxf(fmaf(p1, WINV, b1v), 0.f));
            const uint32_t vb0 = __float_as_uint(v0);
            const uint32_t vb1 = __float_as_uint(v1);

            bool sel0 = false, sel1 = false;
            float m = 0.f;
            #pragma unroll
            for (int it = 0; it < TOPK; ++it) {
                // lane candidate: best unselected, slot0 preferred on intra-lane tie
                bool use0 = false, use1 = false;
                uint32_t cv = 0;
                if (!sel0) { cv = vb0; use0 = true; }
                if (!sel1 && (vb1 > cv || !use0)) { cv = vb1; use1 = true; use0 = false; }
                const uint32_t mx = __reduce_max_sync(0xffffffffu, cv);
                const uint32_t m0 = __ballot_sync(0xffffffffu, use0 && cv == mx);
                const uint32_t m1 = __ballot_sync(0xffffffffu, use1 && cv == mx);
                // winner = smallest global index among cv==mx (slot0 lanes first)
                const int w = m0 ? (__ffs(m0) - 1) : (__ffs(m1) - 1 + 32);
                if (it == 0) m = __uint_as_float(mx);
                sel0 |= (w == lane);
                sel1 |= (w == lane + 32);
            }
            float e0 = sel0 ? __expf(v0 - m) : 0.f;
            float e1 = sel1 ? __expf(v1 - m) : 0.f;
            float sum = e0 + e1;
            #pragma unroll
            for (int off = 16; off; off >>= 1) sum += __shfl_xor_sync(0xffffffffu, sum, off);
            const float inv = 1.f / sum;
            out[gt + lane]        = e0 * inv;
            out[gt + lane + 32]   = e1 * inv;
            maskp[gt + lane]      = sel0 ? 1.f : 0.f;
            maskp[gt + lane + 32] = sel1 ? 1.f : 0.f;
        }
        __syncthreads();
        if (tid == 0) g_cnt[mblk] = 0;        // reset for next graph replay
    }
}

extern "C" void kernel_launch(void* const* d_in, const int* in_sizes, int n_in,
                              void* d_out, int out_size) {
    const float* X    = (const float*)d_in[0];
    const float* W    = (const float*)d_in[1];
    const float* bias = (const float*)d_in[2];
    float* out = (float*)d_out;

    gemm_fused<<<NMB * KSPLIT, 128>>>(X, W, bias, out);
}

// round 16
// speedup vs baseline: 1.0435x; 1.0435x over previous
#include <cuda_runtime.h>
#include <cuda_fp16.h>
#include <stdint.h>

#define TOKENS 16384
#define KDIM   2048
#define EDIM   64
#define TOPK   8
#define BM     64
#define BK     32
#define KSPLIT 4
#define NITH   16              // k-tiles per split (4 x 16 x 32 = 2048)
#define WSCALE 1024.0f
#define WINV   (1.0f / 1024.0f)
#define PHALF  ((size_t)TOKENS * EDIM)

// dynamic smem layout:
//   raw A slots: 3 x 8192B @ 0                      (fp32, 16B-chunk XOR swizzle)
//   split stages: 2 x 16384B @ 24576
//     stage s: Ahi @ +0 (4KB), Alo @ +4096, Bhi @ +8192, Blo @ +12288
#define RAW_SLOT_B  8192
#define SPLIT_BASE  24576
#define SPLIT_STG_B 16384
#define SMEM_K1     (SPLIT_BASE + 2 * SPLIT_STG_B)   // 57344 B

__device__ float g_part[KSPLIT][TOKENS * EDIM];   // 16.8 MB scratch (L2-resident)

__device__ __forceinline__ uint32_t pack2h(__half a, __half b) {
    return (uint32_t)__half_as_ushort(a) | ((uint32_t)__half_as_ushort(b) << 16);
}
__device__ __forceinline__ void mma_f16(float c[4],
                                        uint32_t a0, uint32_t a1, uint32_t a2, uint32_t a3,
                                        uint32_t b0, uint32_t b1) {
    asm volatile(
        "mma.sync.aligned.m16n8k16.row.col.f32.f16.f16.f32 "
        "{%0,%1,%2,%3},{%4,%5,%6,%7},{%8,%9},{%0,%1,%2,%3};\n"
        : "+f"(c[0]), "+f"(c[1]), "+f"(c[2]), "+f"(c[3])
        : "r"(a0), "r"(a1), "r"(a2), "r"(a3), "r"(b0), "r"(b1));
}
__device__ __forceinline__ void split16(float v, __half& h, __half& l) {
    h = __float2half_rn(v);
    l = __float2half_rn(v - __half2float(h));
}
__device__ __forceinline__ uint32_t smem_u32(const void* p) {
    uint32_t a;
    asm("{ .reg .u64 t; cvta.to.shared.u64 t, %1; cvt.u32.u64 %0, t; }" : "=r"(a) : "l"(p));
    return a;
}
__device__ __forceinline__ void cpa16(uint32_t dst, const void* src) {
    asm volatile("cp.async.ca.shared.global [%0], [%1], 16;" :: "r"(dst), "l"(src));
}
#define CPA_COMMIT() asm volatile("cp.async.commit_group;" ::: "memory")
#define CPA_WAIT1()  asm volatile("cp.async.wait_group 1;" ::: "memory")

// ---------------- K1: quarter-K GEMM, cp.async raw-A pipeline ----------------
__global__ void __launch_bounds__(128, 4)
gemm_part(const float* __restrict__ X, const float* __restrict__ W)
{
    extern __shared__ char smem[];
    const uint32_t sbase = smem_u32(smem);

    const int tid  = threadIdx.x;
    const int wrp  = tid >> 5;
    const int lane = tid & 31;
    const int mb   = blockIdx.x * BM;
    const int kb   = blockIdx.y * NITH;      // first k-tile of this split

    const int g  = lane >> 2;
    const int c  = lane & 3;
    const int s4 = ((g >> 1) & 3) << 2;
    const int R0 = (wrp >> 1) << 5;          // warp row base (0/32)
    const int N0 = (wrp & 1) << 5;           // warp col base (0/32)

    // A staging decomposition (self-copy: each thread cp.asyncs what it reads)
    const int ar   = tid >> 1;               // A row 0..63
    const int half = tid & 1;                // row half (16 floats each)
    const int akw  = half << 3;              // A word base 0/8 (for split STS)
    const int asw  = ((ar >> 1) & 3) << 2;   // split-stage swizzle (unchanged)
    const int rsw  = ar & 7;                 // raw-slot 16B-chunk swizzle
    // my 4 raw chunks within my row (swizzled offsets, constant across tiles)
    uint32_t rchk[4];
    #pragma unroll
    for (int j = 0; j < 4; ++j)
        rchk[j] = (uint32_t)(ar * 128 + (((half << 2) + j) ^ rsw) * 16);
    const float* xrow = X + (size_t)(mb + ar) * KDIM + half * 16;

    // B staging decomposition (unchanged R13 path)
    const int bn  = tid & 63;                // B expert 0..63
    const int bkq = tid >> 6;                // B k-quarter 0/1
    const int bkw = bkq << 3;
    const int bsw = ((bn >> 1) & 3) << 2;

    float acc[2][4][4];
    #pragma unroll
    for (int mt = 0; mt < 2; ++mt)
        #pragma unroll
        for (int j = 0; j < 4; ++j)
            #pragma unroll
            for (int q = 0; q < 4; ++q) acc[mt][j][q] = 0.f;

    float wv[16];
    {   // prologue: raw A tiles 0,1 via cp.async; W tile 0 via LDG
        #pragma unroll
        for (int s = 0; s < 2; ++s) {
            const uint32_t dst = sbase + s * RAW_SLOT_B;
            const float* src = xrow + (kb + s) * BK;
            #pragma unroll
            for (int j = 0; j < 4; ++j) cpa16(dst + rchk[j], src + 4 * j);
            CPA_COMMIT();
        }
        const float* wp = W + (size_t)(kb * BK + bkq * 16) * EDIM + bn;
        #pragma unroll
        for (int i = 0; i < 16; ++i) wv[i] = wp[(size_t)i * EDIM];
    }

    #pragma unroll 1
    for (int it = 0; it < NITH; ++it) {
        char* stg = smem + SPLIT_BASE + (it & 1) * SPLIT_STG_B;
        char* Ahi = stg;
        char* Bhi = stg + 8192;

        // ---- my raw A(it) chunks have landed (self-copy => per-thread wait) ----
        CPA_WAIT1();

        // ---- read raw, split to fp16 hi/lo, store swizzled ----
        {
            const char* raw = smem + (it % 3) * RAW_SLOT_B;
            uint4 rq[4];
            #pragma unroll
            for (int j = 0; j < 4; ++j)
                rq[j] = *(const uint4*)(raw + rchk[j]);
            const float* v = (const float*)rq;   // k-order floats half*16 .. +15
            uint32_t ph[8], pl[8];
            #pragma unroll
            for (int i = 0; i < 8; ++i) {
                __half h0, l0, h1, l1;
                split16(v[2 * i],     h0, l0);
                split16(v[2 * i + 1], h1, l1);
                ph[i] = pack2h(h0, h1);
                pl[i] = pack2h(l0, l1);
            }
            char* pa = Ahi + ar * 64;
            const int o0 = ((akw)     ^ asw) << 2;
            const int o1 = ((akw + 4) ^ asw) << 2;
            *(uint4*)(pa + o0)        = make_uint4(ph[0], ph[1], ph[2], ph[3]);
            *(uint4*)(pa + o1)        = make_uint4(ph[4], ph[5], ph[6], ph[7]);
            *(uint4*)(pa + 4096 + o0) = make_uint4(pl[0], pl[1], pl[2], pl[3]);
            *(uint4*)(pa + 4096 + o1) = make_uint4(pl[4], pl[5], pl[6], pl[7]);
        }
        {
            uint32_t ph[8], pl[8];
            #pragma unroll
            for (int i = 0; i < 8; ++i) {
                __half h0, l0, h1, l1;
                split16(wv[2 * i]     * WSCALE, h0, l0);
                split16(wv[2 * i + 1] * WSCALE, h1, l1);
                ph[i] = pack2h(h0, h1);
                pl[i] = pack2h(l0, l1);
            }
            char* pb = Bhi + bn * 64;
            const int o0 = ((bkw)     ^ bsw) << 2;
            const int o1 = ((bkw + 4) ^ bsw) << 2;
            *(uint4*)(pb + o0)        = make_uint4(ph[0], ph[1], ph[2], ph[3]);
            *(uint4*)(pb + o1)        = make_uint4(ph[4], ph[5], ph[6], ph[7]);
            *(uint4*)(pb + 4096 + o0) = make_uint4(pl[0], pl[1], pl[2], pl[3]);
            *(uint4*)(pb + 4096 + o1) = make_uint4(pl[4], pl[5], pl[6], pl[7]);
        }

        // ---- issue raw A(it+2) cp.async (empty commit keeps group count) ----
        if (it + 2 < NITH) {
            const uint32_t dst = sbase + ((it + 2) % 3) * RAW_SLOT_B;
            const float* src = xrow + (kb + it + 2) * BK;
            #pragma unroll
            for (int j = 0; j < 4; ++j) cpa16(dst + rchk[j], src + 4 * j);
        }
        CPA_COMMIT();

        // ---- prefetch next W tile (LDG, L2-hot) ----
        if (it + 1 < NITH) {
            const float* wp = W + (size_t)((kb + it + 1) * BK + bkq * 16) * EDIM + bn;
            #pragma unroll
            for (int i = 0; i < 16; ++i) wv[i] = wp[(size_t)i * EDIM];
        }

        __syncthreads();   // split stage (it&1) visible; double-buffer protects reuse

        // ---- compute: 2 k-chunks; preload frags, product-major MMA issue ----
        #pragma unroll
        for (int kc = 0; kc < 2; ++kc) {
            const int o0 = ((kc * 8 + c)     ^ s4) << 2;
            const int o1 = ((kc * 8 + c + 4) ^ s4) << 2;
            uint32_t ah[2][4], al[2][4];
            #pragma unroll
            for (int mt = 0; mt < 2; ++mt) {
                const char* pa = Ahi + (R0 + mt * 16 + g) * 64;
                ah[mt][0] = *(const uint32_t*)(pa + o0);
                ah[mt][1] = *(const uint32_t*)(pa + 512 + o0);
                ah[mt][2] = *(const uint32_t*)(pa + o1);
                ah[mt][3] = *(const uint32_t*)(pa + 512 + o1);
                al[mt][0] = *(const uint32_t*)(pa + 4096 + o0);
                al[mt][1] = *(const uint32_t*)(pa + 4608 + o0);
                al[mt][2] = *(const uint32_t*)(pa + 4096 + o1);
                al[mt][3] = *(const uint32_t*)(pa + 4608 + o1);
            }
            uint32_t bh[4][2], bl[4][2];
            #pragma unroll
            for (int j = 0; j < 4; ++j) {
                const char* pb = Bhi + (N0 + j * 8 + g) * 64;
                bh[j][0] = *(const uint32_t*)(pb + o0);
                bh[j][1] = *(const uint32_t*)(pb + o1);
                bl[j][0] = *(const uint32_t*)(pb + 4096 + o0);
                bl[j][1] = *(const uint32_t*)(pb + 4096 + o1);
            }
            #pragma unroll
            for (int j = 0; j < 4; ++j)
                #pragma unroll
                for (int mt = 0; mt < 2; ++mt)
                    mma_f16(acc[mt][j], ah[mt][0], ah[mt][1], ah[mt][2], ah[mt][3],
                            bh[j][0], bh[j][1]);
            #pragma unroll
            for (int j = 0; j < 4; ++j)
                #pragma unroll
                for (int mt = 0; mt < 2; ++mt)
                    mma_f16(acc[mt][j], al[mt][0], al[mt][1], al[mt][2], al[mt][3],
                            bh[j][0], bh[j][1]);
            #pragma unroll
            for (int j = 0; j < 4; ++j)
                #pragma unroll
                for (int mt = 0; mt < 2; ++mt)
                    mma_f16(acc[mt][j], ah[mt][0], ah[mt][1], ah[mt][2], ah[mt][3],
                            bl[j][0], bl[j][1]);
        }
        __syncthreads();   // compute done before next iter overwrites split stage
    }

    // ---- write raw partial sums (scaled by WSCALE) to scratch ----
    float* pbase = g_part[blockIdx.y] + (size_t)mb * EDIM;
    #pragma unroll
    for (int mt = 0; mt < 2; ++mt)
        #pragma unroll
        for (int j = 0; j < 4; ++j) {
            const int col = N0 + j * 8 + 2 * c;
            const int r0  = R0 + mt * 16 + g;
            *(float2*)&pbase[(size_t)r0 * EDIM + col] =
                make_float2(acc[mt][j][0], acc[mt][j][1]);
            *(float2*)&pbase[(size_t)(r0 + 8) * EDIM + col] =
                make_float2(acc[mt][j][2], acc[mt][j][3]);
        }
}

// ---------------- K2: combine + bias + ReLU + top-8 + softmax (2-token ILP) ----------------
__global__ void __launch_bounds__(256, 4)
finish_topk(const float* __restrict__ bias, float* __restrict__ out)
{
    const int lane = threadIdx.x & 31;
    const int wrp  = threadIdx.x >> 5;
    const float b0v = bias[lane];
    const float b1v = bias[lane + 32];
    float* maskp = out + PHALF;

    const int t0 = blockIdx.x * 32 + wrp * 4;
    #pragma unroll
    for (int pp = 0; pp < 2; ++pp) {
        size_t gt[2];
        float v0[2], v1[2];
        uint32_t vb0[2], vb1[2];
        #pragma unroll
        for (int t = 0; t < 2; ++t) {
            gt[t] = (size_t)(t0 + 2 * pp + t) * EDIM;
            float p0 = (g_part[0][gt[t] + lane]      + g_part[1][gt[t] + lane])
                     + (g_part[2][gt[t] + lane]      + g_part[3][gt[t] + lane]);
            float p1 = (g_part[0][gt[t] + lane + 32] + g_part[1][gt[t] + lane + 32])
                     + (g_part[2][gt[t] + lane + 32] + g_part[3][gt[t] + lane + 32]);
            // fabsf clears a possible -0 so fp32 bits are order-isomorphic to value
            v0[t] = fabsf(fmaxf(fmaf(p0, WINV, b0v), 0.f));
            v1[t] = fabsf(fmaxf(fmaf(p1, WINV, b1v), 0.f));
            vb0[t] = __float_as_uint(v0[t]);
            vb1[t] = __float_as_uint(v1[t]);
        }

        bool sel0[2] = {false, false}, sel1[2] = {false, false};
        float m[2] = {0.f, 0.f};
        #pragma unroll
        for (int it = 0; it < TOPK; ++it) {
            uint32_t cv[2], ci[2], mx[2], s[2];
            #pragma unroll
            for (int t = 0; t < 2; ++t) {
                cv[t] = 0; ci[t] = 1024;
                if (!sel0[t])                                      { cv[t] = vb0[t]; ci[t] = lane; }
                if (!sel1[t] && (vb1[t] > cv[t] || ci[t] == 1024)) { cv[t] = vb1[t]; ci[t] = lane + 32; }
            }
            mx[0] = __reduce_max_sync(0xffffffffu, cv[0]);
            mx[1] = __reduce_max_sync(0xffffffffu, cv[1]);
            s[0] = __reduce_min_sync(0xffffffffu, (cv[0] == mx[0]) ? ci[0] : 1024u);
            s[1] = __reduce_min_sync(0xffffffffu, (cv[1] == mx[1]) ? ci[1] : 1024u);
            #pragma unroll
            for (int t = 0; t < 2; ++t) {
                if (it == 0) m[t] = __uint_as_float(mx[t]);
                sel0[t] |= (s[t] == (uint32_t)lane);
                sel1[t] |= (s[t] == (uint32_t)(lane + 32));
            }
        }
        #pragma unroll
        for (int t = 0; t < 2; ++t) {
            float e0 = sel0[t] ? expf(v0[t] - m[t]) : 0.f;
            float e1 = sel1[t] ? expf(v1[t] - m[t]) : 0.f;
            float sum = e0 + e1;
            #pragma unroll
            for (int off = 16; off; off >>= 1) sum += __shfl_xor_sync(0xffffffffu, sum, off);
            const float inv = 1.f / sum;
            out[gt[t] + lane]        = e0 * inv;
            out[gt[t] + lane + 32]   = e1 * inv;
            maskp[gt[t] + lane]      = sel0[t] ? 1.f : 0.f;
            maskp[gt[t] + lane + 32] = sel1[t] ? 1.f : 0.f;
        }
    }
}

extern "C" void kernel_launch(void* const* d_in, const int* in_sizes, int n_in,
                              void* d_out, int out_size) {
    const float* X    = (const float*)d_in[0];
    const float* W    = (const float*)d_in[1];
    const float* bias = (const float*)d_in[2];
    float* out = (float*)d_out;

    cudaFuncSetAttribute(gemm_part, cudaFuncAttributeMaxDynamicSharedMemorySize, SMEM_K1);
    dim3 g1(TOKENS / BM, KSPLIT);
    gemm_part<<<g1, 128, SMEM_K1>>>(X, W);
    finish_topk<<<TOKENS / 32, 256>>>(bias, out);
}

// round 17
// speedup vs baseline: 1.3707x; 1.3135x over previous
#include <cuda_runtime.h>
#include <cuda_fp16.h>
#include <stdint.h>

#define TOKENS 16384
#define KDIM   2048
#define EDIM   64
#define TOPK   8
#define BM     64
#define BK     32
#define KSPLIT 4
#define NITH   16              // k-tiles per split (4 x 16 x 32 = 2048)
#define WSCALE 1024.0f
#define WINV   (1.0f / 1024.0f)
#define PHALF  ((size_t)TOKENS * EDIM)

// per-stage staging: Ahi@0 (4KB), Alo@4096, Bhi@8192, Blo@12288  -> 16KB; x2 stages
#define STAGE_B 16384
#define SMEM_K1 (2 * STAGE_B)

__device__ float g_part[KSPLIT][TOKENS * EDIM];   // 16.8 MB scratch (L2-resident)

__device__ __forceinline__ void mma_f16(float c[4],
                                        uint32_t a0, uint32_t a1, uint32_t a2, uint32_t a3,
                                        uint32_t b0, uint32_t b1) {
    asm volatile(
        "mma.sync.aligned.m16n8k16.row.col.f32.f16.f16.f32 "
        "{%0,%1,%2,%3},{%4,%5,%6,%7},{%8,%9},{%0,%1,%2,%3};\n"
        : "+f"(c[0]), "+f"(c[1]), "+f"(c[2]), "+f"(c[3])
        : "r"(a0), "r"(a1), "r"(a2), "r"(a3), "r"(b0), "r"(b1));
}

// packed split: (v0,v1) -> hi pair (return) and lo pair (out). Bit-identical to
// per-element __float2half_rn path; fewer instructions via F2FP.PACK.
__device__ __forceinline__ uint32_t split2(float v0, float v1, uint32_t& lo) {
    __half2 h2 = __floats2half2_rn(v0, v1);
    float2  hf = __half22float2(h2);
    __half2 l2 = __floats2half2_rn(v0 - hf.x, v1 - hf.y);
    lo = *(uint32_t*)&l2;
    return *(uint32_t*)&h2;
}

// ---------------- K1: quarter-K GEMM, partial sums to scratch (R13 pipeline) ----------------
__global__ void __launch_bounds__(128, 4)
gemm_part(const float* __restrict__ X, const float* __restrict__ W)
{
    __shared__ char smem[SMEM_K1];

    const int tid  = threadIdx.x;
    const int wrp  = tid >> 5;
    const int lane = tid & 31;
    const int mb   = blockIdx.x * BM;
    const int kb   = blockIdx.y * NITH;      // first k-tile of this split

    const int g  = lane >> 2;
    const int c  = lane & 3;
    const int s4 = ((g >> 1) & 3) << 2;
    const int R0 = (wrp >> 1) << 5;          // warp row base (0/32)
    const int N0 = (wrp & 1) << 5;           // warp col base (0/32)

    // staging decomposition (128 threads)
    const int ar  = tid >> 1;                // A row 0..63
    const int akw = (tid & 1) << 3;          // A word base 0/8
    const int asw = ((ar >> 1) & 3) << 2;
    const int bn  = tid & 63;                // B expert 0..63
    const int bkq = tid >> 6;                // B k-quarter 0/1
    const int bkw = bkq << 3;
    const int bsw = ((bn >> 1) & 3) << 2;

    float acc[2][4][4];
    #pragma unroll
    for (int mt = 0; mt < 2; ++mt)
        #pragma unroll
        for (int j = 0; j < 4; ++j)
            #pragma unroll
            for (int q = 0; q < 4; ++q) acc[mt][j][q] = 0.f;

    float4 xa[4];
    float  wv[16];
    {   // prefetch tile 0 of this split
        const float* xp = X + (size_t)(mb + ar) * KDIM + kb * BK + (akw << 1);
        #pragma unroll
        for (int p = 0; p < 4; ++p) xa[p] = *(const float4*)(xp + 4 * p);
        const float* wp = W + (size_t)(kb * BK + bkq * 16) * EDIM + bn;
        #pragma unroll
        for (int i = 0; i < 16; ++i) wv[i] = wp[(size_t)i * EDIM];
    }

    #pragma unroll 1
    for (int it = 0; it < NITH; ++it) {
        char* Ahi = smem + (it & 1) * STAGE_B;
        char* Bhi = Ahi + 8192;

        // ---- store staged tile (fp16 hi/lo split), swizzled ----
        {
            float v[16] = {xa[0].x, xa[0].y, xa[0].z, xa[0].w,
                           xa[1].x, xa[1].y, xa[1].z, xa[1].w,
                           xa[2].x, xa[2].y, xa[2].z, xa[2].w,
                           xa[3].x, xa[3].y, xa[3].z, xa[3].w};
            uint32_t ph[8], pl[8];
            #pragma unroll
            for (int i = 0; i < 8; ++i)
                ph[i] = split2(v[2 * i], v[2 * i + 1], pl[i]);
            char* pa = Ahi + ar * 64;
            const int o0 = ((akw)     ^ asw) << 2;
            const int o1 = ((akw + 4) ^ asw) << 2;
            *(uint4*)(pa + o0)        = make_uint4(ph[0], ph[1], ph[2], ph[3]);
            *(uint4*)(pa + o1)        = make_uint4(ph[4], ph[5], ph[6], ph[7]);
            *(uint4*)(pa + 4096 + o0) = make_uint4(pl[0], pl[1], pl[2], pl[3]);
            *(uint4*)(pa + 4096 + o1) = make_uint4(pl[4], pl[5], pl[6], pl[7]);
        }
        {
            uint32_t ph[8], pl[8];
            #pragma unroll
            for (int i = 0; i < 8; ++i)
                ph[i] = split2(wv[2 * i] * WSCALE, wv[2 * i + 1] * WSCALE, pl[i]);
            char* pb = Bhi + bn * 64;
            const int o0 = ((bkw)     ^ bsw) << 2;
            const int o1 = ((bkw + 4) ^ bsw) << 2;
            *(uint4*)(pb + o0)        = make_uint4(ph[0], ph[1], ph[2], ph[3]);
            *(uint4*)(pb + o1)        = make_uint4(ph[4], ph[5], ph[6], ph[7]);
            *(uint4*)(pb + 4096 + o0) = make_uint4(pl[0], pl[1], pl[2], pl[3]);
            *(uint4*)(pb + 4096 + o1) = make_uint4(pl[4], pl[5], pl[6], pl[7]);
        }
        __syncthreads();   // single barrier per iteration (double buffer)

        // ---- prefetch next tile ----
        if (it + 1 < NITH) {
            const int nk = kb + it + 1;
            const float* xp = X + (size_t)(mb + ar) * KDIM + nk * BK + (akw << 1);
            #pragma unroll
            for (int p = 0; p < 4; ++p) xa[p] = *(const float4*)(xp + 4 * p);
            const float* wp = W + (size_t)(nk * BK + bkq * 16) * EDIM + bn;
            #pragma unroll
            for (int i = 0; i < 16; ++i) wv[i] = wp[(size_t)i * EDIM];
        }

        // ---- compute: 2 k-chunks; preload frags, product-major MMA issue ----
        #pragma unroll
        for (int kc = 0; kc < 2; ++kc) {
            const int o0 = ((kc * 8 + c)     ^ s4) << 2;
            const int o1 = ((kc * 8 + c + 4) ^ s4) << 2;
            uint32_t ah[2][4], al[2][4];
            #pragma unroll
            for (int mt = 0; mt < 2; ++mt) {
                const char* pa = Ahi + (R0 + mt * 16 + g) * 64;
                ah[mt][0] = *(const uint32_t*)(pa + o0);
                ah[mt][1] = *(const uint32_t*)(pa + 512 + o0);
                ah[mt][2] = *(const uint32_t*)(pa + o1);
                ah[mt][3] = *(const uint32_t*)(pa + 512 + o1);
                al[mt][0] = *(const uint32_t*)(pa + 4096 + o0);
                al[mt][1] = *(const uint32_t*)(pa + 4608 + o0);
                al[mt][2] = *(const uint32_t*)(pa + 4096 + o1);
                al[mt][3] = *(const uint32_t*)(pa + 4608 + o1);
            }
            uint32_t bh[4][2], bl[4][2];
            #pragma unroll
            for (int j = 0; j < 4; ++j) {
                const char* pb = Bhi + (N0 + j * 8 + g) * 64;
                bh[j][0] = *(const uint32_t*)(pb + o0);
                bh[j][1] = *(const uint32_t*)(pb + o1);
                bl[j][0] = *(const uint32_t*)(pb + 4096 + o0);
                bl[j][1] = *(const uint32_t*)(pb + 4096 + o1);
            }
            #pragma unroll
            for (int j = 0; j < 4; ++j)
                #pragma unroll
                for (int mt = 0; mt < 2; ++mt)
                    mma_f16(acc[mt][j], ah[mt][0], ah[mt][1], ah[mt][2], ah[mt][3],
                            bh[j][0], bh[j][1]);
            #pragma unroll
            for (int j = 0; j < 4; ++j)
                #pragma unroll
                for (int mt = 0; mt < 2; ++mt)
                    mma_f16(acc[mt][j], al[mt][0], al[mt][1], al[mt][2], al[mt][3],
                            bh[j][0], bh[j][1]);
            #pragma unroll
            for (int j = 0; j < 4; ++j)
                #pragma unroll
                for (int mt = 0; mt < 2; ++mt)
                    mma_f16(acc[mt][j], ah[mt][0], ah[mt][1], ah[mt][2], ah[mt][3],
                            bl[j][0], bl[j][1]);
        }
    }

    // ---- write raw partial sums (scaled by WSCALE) to scratch ----
    float* pbase = g_part[blockIdx.y] + (size_t)mb * EDIM;
    #pragma unroll
    for (int mt = 0; mt < 2; ++mt)
        #pragma unroll
        for (int j = 0; j < 4; ++j) {
            const int col = N0 + j * 8 + 2 * c;
            const int r0  = R0 + mt * 16 + g;
            *(float2*)&pbase[(size_t)r0 * EDIM + col] =
                make_float2(acc[mt][j][0], acc[mt][j][1]);
            *(float2*)&pbase[(size_t)(r0 + 8) * EDIM + col] =
                make_float2(acc[mt][j][2], acc[mt][j][3]);
        }
}

// ---------------- K2: combine + bias + ReLU + top-8 + softmax (2-token ILP, 1024 blocks) ----------------
__global__ void __launch_bounds__(256, 4)
finish_topk(const float* __restrict__ bias, float* __restrict__ out)
{
    const int lane = threadIdx.x & 31;
    const int wrp  = threadIdx.x >> 5;
    const float b0v = bias[lane];
    const float b1v = bias[lane + 32];
    float* maskp = out + PHALF;

    const int t0 = blockIdx.x * 16 + wrp * 2;
    size_t gt[2];
    float v0[2], v1[2];
    uint32_t vb0[2], vb1[2];
    #pragma unroll
    for (int t = 0; t < 2; ++t) {
        gt[t] = (size_t)(t0 + t) * EDIM;
        float p0 = (g_part[0][gt[t] + lane]      + g_part[1][gt[t] + lane])
                 + (g_part[2][gt[t] + lane]      + g_part[3][gt[t] + lane]);
        float p1 = (g_part[0][gt[t] + lane + 32] + g_part[1][gt[t] + lane + 32])
                 + (g_part[2][gt[t] + lane + 32] + g_part[3][gt[t] + lane + 32]);
        // fabsf clears a possible -0 so fp32 bits are order-isomorphic to value
        v0[t] = fabsf(fmaxf(fmaf(p0, WINV, b0v), 0.f));
        v1[t] = fabsf(fmaxf(fmaf(p1, WINV, b1v), 0.f));
        vb0[t] = __float_as_uint(v0[t]);
        vb1[t] = __float_as_uint(v1[t]);
    }

    bool sel0[2] = {false, false}, sel1[2] = {false, false};
    float m[2] = {0.f, 0.f};
    #pragma unroll
    for (int it = 0; it < TOPK; ++it) {
        uint32_t cv[2], ci[2], mx[2], s[2];
        #pragma unroll
        for (int t = 0; t < 2; ++t) {
            cv[t] = 0; ci[t] = 1024;
            if (!sel0[t])                                      { cv[t] = vb0[t]; ci[t] = lane; }
            if (!sel1[t] && (vb1[t] > cv[t] || ci[t] == 1024)) { cv[t] = vb1[t]; ci[t] = lane + 32; }
        }
        mx[0] = __reduce_max_sync(0xffffffffu, cv[0]);
        mx[1] = __reduce_max_sync(0xffffffffu, cv[1]);
        s[0] = __reduce_min_sync(0xffffffffu, (cv[0] == mx[0]) ? ci[0] : 1024u);
        s[1] = __reduce_min_sync(0xffffffffu, (cv[1] == mx[1]) ? ci[1] : 1024u);
        #pragma unroll
        for (int t = 0; t < 2; ++t) {
            if (it == 0) m[t] = __uint_as_float(mx[t]);
            sel0[t] |= (s[t] == (uint32_t)lane);
            sel1[t] |= (s[t] == (uint32_t)(lane + 32));
        }
    }
    #pragma unroll
    for (int t = 0; t < 2; ++t) {
        float e0 = sel0[t] ? expf(v0[t] - m[t]) : 0.f;
        float e1 = sel1[t] ? expf(v1[t] - m[t]) : 0.f;
        float sum = e0 + e1;
        #pragma unroll
        for (int off = 16; off; off >>= 1) sum += __shfl_xor_sync(0xffffffffu, sum, off);
        const float inv = 1.f / sum;
        out[gt[t] + lane]        = e0 * inv;
        out[gt[t] + lane + 32]   = e1 * inv;
        maskp[gt[t] + lane]      = sel0[t] ? 1.f : 0.f;
        maskp[gt[t] + lane + 32] = sel1[t] ? 1.f : 0.f;
    }
}

extern "C" void kernel_launch(void* const* d_in, const int* in_sizes, int n_in,
                              void* d_out, int out_size) {
    const float* X    = (const float*)d_in[0];
    const float* W    = (const float*)d_in[1];
    const float* bias = (const float*)d_in[2];
    float* out = (float*)d_out;

    dim3 g1(TOKENS / BM, KSPLIT);
    gemm_part<<<g1, 128>>>(X, W);
    finish_topk<<<TOKENS / 16, 256>>>(bias, out);
}